// round 16
// baseline (speedup 1.0000x reference)
#include <cuda_runtime.h>
#include <cuda_fp16.h>
#include <cstdint>

#define IC 1152
#define BB 256
#define NU 10
#define US 16
#define DU 160   /* NU*US */
#define IU 8
#define KK (IC*IU)   /* 9216 */
#define KS 36        /* k-split for s-GEMM: chunk = 9216/36 = 256 rows = 32 channels */

#define SA 24    // As smem stride (halfs)
#define SB 168   // Bs smem stride (halfs)

// ---- scratch (__device__ globals per allocation rules) ----
__device__ __align__(16) __half g_Xh [(size_t)BB * KK];   // [b][c*8+i]  4.7MB
__device__ __align__(16) __half g_XhT[(size_t)KK * BB];   // [c*8+i][b]  4.7MB
__device__ __align__(16) __half g_Wt [(size_t)KK * DU];   // [c*8+i][du] 2.9MB
__device__ __align__(16) __half g_Vh [BB * DU];           // v fp16
__device__ __align__(16) float  g_Sp [(size_t)KS * BB * DU]; // s partials 5.9MB
__device__ float g_Bij[IC * NU];                          // routing logits
__device__ float g_Z[3 * NU];                             // per-iteration softmax denominators

// ---------------------------------------------------------------------------
__device__ __forceinline__ uint32_t smem_u32(const void* p) {
    return (uint32_t)__cvta_generic_to_shared(p);
}
__device__ __forceinline__ void ldsm_x4(uint32_t& a0, uint32_t& a1, uint32_t& a2,
                                        uint32_t& a3, uint32_t addr) {
    asm volatile("ldmatrix.sync.aligned.m8n8.x4.shared.b16 {%0,%1,%2,%3}, [%4];"
                 : "=r"(a0), "=r"(a1), "=r"(a2), "=r"(a3) : "r"(addr));
}
__device__ __forceinline__ void ldsm_x2t(uint32_t& b0, uint32_t& b1, uint32_t addr) {
    asm volatile("ldmatrix.sync.aligned.m8n8.x2.trans.shared.b16 {%0,%1}, [%2];"
                 : "=r"(b0), "=r"(b1) : "r"(addr));
}
__device__ __forceinline__ void mma16816(float& c0, float& c1, float& c2, float& c3,
                                         uint32_t a0, uint32_t a1, uint32_t a2, uint32_t a3,
                                         uint32_t b0, uint32_t b1) {
    asm volatile("mma.sync.aligned.m16n8k16.row.col.f32.f16.f16.f32 "
                 "{%0,%1,%2,%3}, {%4,%5,%6,%7}, {%8,%9}, {%0,%1,%2,%3};"
                 : "+f"(c0), "+f"(c1), "+f"(c2), "+f"(c3)
                 : "r"(a0), "r"(a1), "r"(a2), "r"(a3), "r"(b0), "r"(b1));
}

// ---------------------------------------------------------------------------
// fused prep: one pass over x produces BOTH Xh[b][c*8+i] and XhT[c*8+i][b].
// grid (IC/32, BB/64), block 256. Tile: 32 channels x 64 batches x 8 i.
// ---------------------------------------------------------------------------
__global__ void __launch_bounds__(256) k_prep_x(const float* __restrict__ x) {
    __shared__ __half s[8][32][65];   // [i][cl][bl], stride 65 -> conflict-free
    const int c0 = blockIdx.x * 32, b0 = blockIdx.y * 64;
    const int t = threadIdx.x;

    // load: float4 over c (8 float4 per 32 channels)
#pragma unroll
    for (int it = 0; it < 16; it++) {
        const int idx = t + it * 256;
        const int c4 = idx & 7, i = (idx >> 3) & 7, bl = idx >> 6;
        const float4 f = *reinterpret_cast<const float4*>(
            &x[((b0 + bl) * IU + i) * IC + c0 + c4 * 4]);
        s[i][c4 * 4 + 0][bl] = __float2half_rn(f.x);
        s[i][c4 * 4 + 1][bl] = __float2half_rn(f.y);
        s[i][c4 * 4 + 2][bl] = __float2half_rn(f.z);
        s[i][c4 * 4 + 3][bl] = __float2half_rn(f.w);
    }
    __syncthreads();

    // write Xh: thread per (bl, cl)
#pragma unroll
    for (int it = 0; it < 8; it++) {
        const int idx = t + it * 256;
        const int cl = idx & 31, bl = idx >> 5;
        __half h[8];
#pragma unroll
        for (int i = 0; i < 8; i++) h[i] = s[i][cl][bl];
        *reinterpret_cast<uint4*>(&g_Xh[(size_t)(b0 + bl) * KK + (c0 + cl) * 8]) =
            *reinterpret_cast<uint4*>(h);
    }
    // write XhT: thread per (cl, i, b8)
#pragma unroll
    for (int it = 0; it < 8; it++) {
        const int idx = t + it * 256;
        const int b8 = idx & 7, i = (idx >> 3) & 7, cl = idx >> 6;
        __half h[8];
#pragma unroll
        for (int j = 0; j < 8; j++) h[j] = s[i][cl][b8 * 8 + j];
        *reinterpret_cast<uint4*>(
            &g_XhT[(size_t)((c0 + cl) * 8 + i) * BB + b0 + b8 * 8]) =
            *reinterpret_cast<uint4*>(h);
    }
}

// prep: Wt[c*8+i][du] = fp16(W[c][du][i]); also zero b_ij and Z slots
__global__ void __launch_bounds__(160) k_prep_wt(const float* __restrict__ W) {
    __shared__ __half sw[8][168];
    const int c = blockIdx.x, t = threadIdx.x;  // t = du
    if (c == 0) {
        for (int i = t; i < IC * NU; i += 160) g_Bij[i] = 0.0f;
        if (t < 3 * NU) g_Z[t] = 0.0f;
    }
    const float4* wp = reinterpret_cast<const float4*>(&W[(c * DU + t) * IU]);
    const float4 w0 = wp[0], w1 = wp[1];
    sw[0][t] = __float2half_rn(w0.x); sw[1][t] = __float2half_rn(w0.y);
    sw[2][t] = __float2half_rn(w0.z); sw[3][t] = __float2half_rn(w0.w);
    sw[4][t] = __float2half_rn(w1.x); sw[5][t] = __float2half_rn(w1.y);
    sw[6][t] = __float2half_rn(w1.z); sw[7][t] = __float2half_rn(w1.w);
    __syncthreads();
    const int i = t / 20, v = (t % 20) * 8;
    *reinterpret_cast<uint4*>(&g_Wt[(size_t)(c * 8 + i) * DU + v]) =
        *reinterpret_cast<const uint4*>(&sw[i][v]);
}

// ---------------------------------------------------------------------------
// s-GEMM: KS=36 (chunk 256 rows = 32 channels), BM=32, 8 m-tiles.
// grid (36, 8) = 288 blocks, block 256 = 8 warps (2 m x 4 n).
// Fused unnormalized softmax: B scaled by exp(b_ij); Z by mt==0 blocks.
// ---------------------------------------------------------------------------
__global__ void __launch_bounds__(256) k_sgemm(int it) {
    __shared__ __half As[32 * SA];
    __shared__ __half Bs[16 * SB];
    __shared__ float se[32 * NU];    // exp(b_ij) for this chunk's 32 channels
    const int ks = blockIdx.x, mt = blockIdx.y;
    const int m0 = mt * 32, k0 = ks * 256, cch0 = ks * 32;
    const int t = threadIdx.x, lane = t & 31, w = t >> 5;
    const int wm = w & 1, wn = w >> 1;   // 2 m-tiles of 16, 4 n-groups of 40

    // exp table: 320 entries — STRIDE loop (320 > 256 threads)
    for (int idx = t; idx < 32 * NU; idx += 256) {
        const int cl = idx / NU, d = idx % NU;
        se[idx] = __expf(g_Bij[(cch0 + cl) * NU + d]);
    }
    __syncthreads();
    if (mt == 0 && t < NU) {
        float z = 0.0f;
#pragma unroll
        for (int cl = 0; cl < 32; cl++) z += se[cl * NU + t];
        atomicAdd(&g_Z[it * NU + t], z);
    }

    float acc[5][4];
#pragma unroll
    for (int i = 0; i < 5; i++)
#pragma unroll
        for (int j = 0; j < 4; j++) acc[i][j] = 0.0f;

    const uint32_t aaddr =
        smem_u32(&As[(wm * 16 + (lane & 15)) * SA + ((lane >> 4) << 3)]);
    const uint32_t baddr0 = smem_u32(&Bs[(lane & 15) * SB + wn * 40]);

    for (int kk = 0; kk < 16; kk++) {
        const int kg = k0 + kk * 16;
        // stage A: 32 x 16 halfs (64 threads)
        if (t < 64) {
            const int r = t >> 1, p = t & 1;
            *reinterpret_cast<uint4*>(&As[r * SA + p * 8]) =
                *reinterpret_cast<const uint4*>(&g_Xh[(size_t)(m0 + r) * KK + kg + p * 8]);
        }
        // stage B: 16 x 160 halfs, scaled by exp(b_ij)
        for (int idx = t; idx < 320; idx += 256) {
            const int kr = idx / 20, n8 = (idx % 20) * 8;
            const int cl = kk * 2 + (kr >> 3), d = n8 >> 4;
            const __half2 s2 = __float2half2_rn(se[cl * NU + d]);
            uint4 raw = *reinterpret_cast<const uint4*>(&g_Wt[(size_t)(kg + kr) * DU + n8]);
            __half2* h = reinterpret_cast<__half2*>(&raw);
#pragma unroll
            for (int j = 0; j < 4; j++) h[j] = __hmul2(h[j], s2);
            *reinterpret_cast<uint4*>(&Bs[kr * SB + n8]) = raw;
        }
        __syncthreads();
        uint32_t a0, a1, a2, a3;
        ldsm_x4(a0, a1, a2, a3, aaddr);
#pragma unroll
        for (int nt = 0; nt < 5; nt++) {
            uint32_t b0, b1;
            ldsm_x2t(b0, b1, baddr0 + nt * 16);
            mma16816(acc[nt][0], acc[nt][1], acc[nt][2], acc[nt][3],
                     a0, a1, a2, a3, b0, b1);
        }
        __syncthreads();
    }
    // epilogue: write partials
    const int rg = lane >> 2, cb = (lane & 3) * 2;
    const int m = m0 + wm * 16 + rg;
#pragma unroll
    for (int nt = 0; nt < 5; nt++) {
        const int n = wn * 40 + nt * 8 + cb;
        float2 lo = make_float2(acc[nt][0], acc[nt][1]);
        float2 hi = make_float2(acc[nt][2], acc[nt][3]);
        *reinterpret_cast<float2*>(&g_Sp[((size_t)ks * BB + m) * DU + n]) = lo;
        *reinterpret_cast<float2*>(&g_Sp[((size_t)ks * BB + m + 8) * DU + n]) = hi;
    }
}

// ---------------------------------------------------------------------------
// squash: sum KS=36 partials, normalize by Z_d, squash, write vout + Vh.
// grid 256 (b), block 320: du4 = t%40 (4 du), g = t/40 (8 groups; ks = g+8j).
// ---------------------------------------------------------------------------
__global__ void __launch_bounds__(320) k_squash(float* __restrict__ vout, int it) {
    __shared__ float4 sred[8][40];
    __shared__ float sv[DU];
    __shared__ float msq[US];
    const int b = blockIdx.x, t = threadIdx.x;
    const int du4 = t % 40, g = t / 40;   // g in [0,8)

    float4 s = make_float4(0.f, 0.f, 0.f, 0.f);
#pragma unroll
    for (int j = 0; j < 5; j++) {
        const int ks = g + j * 8;
        if (ks < KS) {
            const float4 p = *reinterpret_cast<const float4*>(
                &g_Sp[((size_t)ks * BB + b) * DU + du4 * 4]);
            s.x += p.x; s.y += p.y; s.z += p.z; s.w += p.w;
        }
    }
    sred[g][du4] = s;
    __syncthreads();

    if (t < 40) {
        float4 a = sred[0][t];
#pragma unroll
        for (int g2 = 1; g2 < 8; g2++) {
            const float4 p = sred[g2][t];
            a.x += p.x; a.y += p.y; a.z += p.z; a.w += p.w;
        }
        const float inv = 1.0f / g_Z[it * NU + (t >> 2)];
        a.x *= inv; a.y *= inv; a.z *= inv; a.w *= inv;
        *reinterpret_cast<float4*>(&sv[t * 4]) = a;
    }
    __syncthreads();
    if (t < US) {
        float m = 0.0f;
#pragma unroll
        for (int d = 0; d < NU; d++) {
            const float v = sv[d * US + t];
            m += v * v;
        }
        msq[t] = m;
    }
    __syncthreads();
    if (t < DU) {
        const float m = msq[t & 15];
        const float scale = sqrtf(m) / (1.0f + m);
        const float v = sv[t] * scale;
        vout[b * DU + t] = v;
        g_Vh[b * DU + t] = __float2half_rn(v);
    }
}

// ---------------------------------------------------------------------------
// agree-GEMM, batch-split 2-way for occupancy: grid (72, 2, 2) = 288 blocks.
//   acc[ci,du] = sum_{b in half} XhT[ci,b] * Vh[b,du]
//   b_ij[c,d] += atomicAdd (1/B) sum_{i,u} Wt*acc   (collision degree 2)
// ---------------------------------------------------------------------------
__global__ void __launch_bounds__(256) k_agree() {
    __shared__ __half As[128 * SA];
    __shared__ __half Bs[16 * SB];
    const int mt = blockIdx.x, nb = blockIdx.y, bs = blockIdx.z;
    const int m0 = mt * 128, n0 = nb * 80, kb0 = bs * 128;
    const int t = threadIdx.x, lane = t & 31, w = t >> 5;

    float acc[10][4];
#pragma unroll
    for (int i = 0; i < 10; i++)
#pragma unroll
        for (int j = 0; j < 4; j++) acc[i][j] = 0.0f;

    const uint32_t aaddr =
        smem_u32(&As[(w * 16 + (lane & 15)) * SA + ((lane >> 4) << 3)]);
    const uint32_t baddr0 = smem_u32(&Bs[(lane & 15) * SB]);

    for (int kk = 0; kk < 8; kk++) {
        const int kg = kb0 + kk * 16;  // batch index base
        {   // stage A: 128 x 16
            const int r = t >> 1, p = t & 1;
            *reinterpret_cast<uint4*>(&As[r * SA + p * 8]) =
                *reinterpret_cast<const uint4*>(&g_XhT[(size_t)(m0 + r) * BB + kg + p * 8]);
        }
        if (t < 160) {  // stage B: 16 x 80 from Vh
            const int kr = t / 10, n8 = (t % 10) * 8;
            *reinterpret_cast<uint4*>(&Bs[kr * SB + n8]) =
                *reinterpret_cast<const uint4*>(&g_Vh[(kg + kr) * DU + n0 + n8]);
        }
        __syncthreads();
        uint32_t a0, a1, a2, a3;
        ldsm_x4(a0, a1, a2, a3, aaddr);
#pragma unroll
        for (int nt = 0; nt < 10; nt++) {
            uint32_t b0, b1;
            ldsm_x2t(b0, b1, baddr0 + nt * 16);
            mma16816(acc[nt][0], acc[nt][1], acc[nt][2], acc[nt][3],
                     a0, a1, a2, a3, b0, b1);
        }
        __syncthreads();
    }
    // fused epilogue: multiply by Wt, reduce over (i,u)
    const int rg = lane >> 2, cb = (lane & 3) * 2;
    const int row0 = m0 + w * 16 + rg;
    float part[2][5];
#pragma unroll
    for (int cl = 0; cl < 2; cl++)
#pragma unroll
        for (int dl = 0; dl < 5; dl++) part[cl][dl] = 0.0f;
#pragma unroll
    for (int nt = 0; nt < 10; nt++) {
        const int dl = nt >> 1;
        const int col = n0 + nt * 8 + cb;
        const float2 f0 = __half22float2(
            *reinterpret_cast<const __half2*>(&g_Wt[(size_t)row0 * DU + col]));
        const float2 f1 = __half22float2(
            *reinterpret_cast<const __half2*>(&g_Wt[(size_t)(row0 + 8) * DU + col]));
        part[0][dl] += f0.x * acc[nt][0] + f0.y * acc[nt][1];
        part[1][dl] += f1.x * acc[nt][2] + f1.y * acc[nt][3];
    }
#pragma unroll
    for (int cl = 0; cl < 2; cl++)
#pragma unroll
        for (int dl = 0; dl < 5; dl++) {
            float v = part[cl][dl];
#pragma unroll
            for (int off = 16; off > 0; off >>= 1)
                v += __shfl_xor_sync(0xffffffffu, v, off);
            if (lane == 0) {
                const int c = (m0 + w * 16) / 8 + cl;
                const int d = nb * 5 + dl;
                atomicAdd(&g_Bij[c * NU + d], v * (1.0f / 256.0f));
            }
        }
}

// ---------------------------------------------------------------------------
extern "C" void kernel_launch(void* const* d_in, const int* in_sizes, int n_in,
                              void* d_out, int out_size) {
    const float* x;
    const float* W;
    if (in_sizes[0] == BB * IU * IC) {
        x = (const float*)d_in[0];
        W = (const float*)d_in[1];
    } else {
        W = (const float*)d_in[0];
        x = (const float*)d_in[1];
    }
    float* out = (float*)d_out;

    k_prep_x<<<dim3(IC / 32, BB / 64), 256>>>(x);
    k_prep_wt<<<IC, 160>>>(W);
    for (int it = 0; it < 3; it++) {
        k_sgemm<<<dim3(KS, 8), 256>>>(it);
        k_squash<<<BB, 320>>>(out, it);
        if (it < 2) k_agree<<<dim3(72, 2, 2), 256>>>();
    }
}

// round 17
// speedup vs baseline: 1.1446x; 1.1446x over previous
#include <cuda_runtime.h>
#include <cuda_fp16.h>
#include <cstdint>

#define IC 1152
#define BB 256
#define NU 10
#define US 16
#define DU 160   /* NU*US */
#define IU 8
#define KK (IC*IU)   /* 9216 */
#define KS 72        /* k-split for s-GEMM: chunk = 9216/72 = 128 rows = 16 channels */

#define SA 24    // As smem stride (halfs)
#define SB 168   // Bs smem stride (halfs)
#define GRID_R 288u

// ---- scratch (__device__ globals per allocation rules) ----
__device__ __align__(16) __half g_Xh [(size_t)BB * KK];   // [b][c*8+i]  4.7MB
__device__ __align__(16) __half g_XhT[(size_t)KK * BB];   // [c*8+i][b]  4.7MB
__device__ __align__(16) __half g_Wt [(size_t)KK * DU];   // [c*8+i][du] 2.9MB
__device__ __align__(16) __half g_Vh [BB * DU];           // v fp16
__device__ __align__(16) float  g_Sp [(size_t)KS * BB * DU]; // s partials 11.8MB
__device__ float g_Bij[IC * NU];                          // routing logits
__device__ float g_Z[3 * NU];                             // per-iteration softmax denominators
__device__ unsigned g_bar;                                // grid barrier counter

// ---------------------------------------------------------------------------
__device__ __forceinline__ uint32_t smem_u32(const void* p) {
    return (uint32_t)__cvta_generic_to_shared(p);
}
__device__ __forceinline__ void ldsm_x4(uint32_t& a0, uint32_t& a1, uint32_t& a2,
                                        uint32_t& a3, uint32_t addr) {
    asm volatile("ldmatrix.sync.aligned.m8n8.x4.shared.b16 {%0,%1,%2,%3}, [%4];"
                 : "=r"(a0), "=r"(a1), "=r"(a2), "=r"(a3) : "r"(addr));
}
__device__ __forceinline__ void ldsm_x2t(uint32_t& b0, uint32_t& b1, uint32_t addr) {
    asm volatile("ldmatrix.sync.aligned.m8n8.x2.trans.shared.b16 {%0,%1}, [%2];"
                 : "=r"(b0), "=r"(b1) : "r"(addr));
}
__device__ __forceinline__ void mma16816(float& c0, float& c1, float& c2, float& c3,
                                         uint32_t a0, uint32_t a1, uint32_t a2, uint32_t a3,
                                         uint32_t b0, uint32_t b1) {
    asm volatile("mma.sync.aligned.m16n8k16.row.col.f32.f16.f16.f32 "
                 "{%0,%1,%2,%3}, {%4,%5,%6,%7}, {%8,%9}, {%0,%1,%2,%3};"
                 : "+f"(c0), "+f"(c1), "+f"(c2), "+f"(c3)
                 : "r"(a0), "r"(a1), "r"(a2), "r"(a3), "r"(b0), "r"(b1));
}

// software grid barrier: release-fence, arrive, spin (thread 0), block fence
__device__ __forceinline__ void grid_bar(unsigned target) {
    __syncthreads();
    if (threadIdx.x == 0) {
        __threadfence();
        atomicAdd(&g_bar, 1u);
        unsigned v = *reinterpret_cast<volatile unsigned*>(&g_bar);
        while (v < target) {
            __nanosleep(64);
            v = *reinterpret_cast<volatile unsigned*>(&g_bar);
        }
    }
    __syncthreads();
}

// ---------------------------------------------------------------------------
// fused prep: one pass over x produces BOTH Xh[b][c*8+i] and XhT[c*8+i][b].
// grid (IC/32, BB/64), block 256.
// ---------------------------------------------------------------------------
__global__ void __launch_bounds__(256) k_prep_x(const float* __restrict__ x) {
    __shared__ __half s[8][32][65];
    const int c0 = blockIdx.x * 32, b0 = blockIdx.y * 64;
    const int t = threadIdx.x;

#pragma unroll
    for (int it = 0; it < 16; it++) {
        const int idx = t + it * 256;
        const int c4 = idx & 7, i = (idx >> 3) & 7, bl = idx >> 6;
        const float4 f = *reinterpret_cast<const float4*>(
            &x[((b0 + bl) * IU + i) * IC + c0 + c4 * 4]);
        s[i][c4 * 4 + 0][bl] = __float2half_rn(f.x);
        s[i][c4 * 4 + 1][bl] = __float2half_rn(f.y);
        s[i][c4 * 4 + 2][bl] = __float2half_rn(f.z);
        s[i][c4 * 4 + 3][bl] = __float2half_rn(f.w);
    }
    __syncthreads();

#pragma unroll
    for (int it = 0; it < 8; it++) {
        const int idx = t + it * 256;
        const int cl = idx & 31, bl = idx >> 5;
        __half h[8];
#pragma unroll
        for (int i = 0; i < 8; i++) h[i] = s[i][cl][bl];
        *reinterpret_cast<uint4*>(&g_Xh[(size_t)(b0 + bl) * KK + (c0 + cl) * 8]) =
            *reinterpret_cast<uint4*>(h);
    }
#pragma unroll
    for (int it = 0; it < 8; it++) {
        const int idx = t + it * 256;
        const int b8 = idx & 7, i = (idx >> 3) & 7, cl = idx >> 6;
        __half h[8];
#pragma unroll
        for (int j = 0; j < 8; j++) h[j] = s[i][cl][b8 * 8 + j];
        *reinterpret_cast<uint4*>(
            &g_XhT[(size_t)((c0 + cl) * 8 + i) * BB + b0 + b8 * 8]) =
            *reinterpret_cast<uint4*>(h);
    }
}

// prep: Wt transpose; zero b_ij, Z slots, barrier counter
__global__ void __launch_bounds__(160) k_prep_wt(const float* __restrict__ W) {
    __shared__ __half sw[8][168];
    const int c = blockIdx.x, t = threadIdx.x;
    if (c == 0) {
        for (int i = t; i < IC * NU; i += 160) g_Bij[i] = 0.0f;
        if (t < 3 * NU) g_Z[t] = 0.0f;
        if (t == 0) g_bar = 0u;
    }
    const float4* wp = reinterpret_cast<const float4*>(&W[(c * DU + t) * IU]);
    const float4 w0 = wp[0], w1 = wp[1];
    sw[0][t] = __float2half_rn(w0.x); sw[1][t] = __float2half_rn(w0.y);
    sw[2][t] = __float2half_rn(w0.z); sw[3][t] = __float2half_rn(w0.w);
    sw[4][t] = __float2half_rn(w1.x); sw[5][t] = __float2half_rn(w1.y);
    sw[6][t] = __float2half_rn(w1.z); sw[7][t] = __float2half_rn(w1.w);
    __syncthreads();
    const int i = t / 20, v = (t % 20) * 8;
    *reinterpret_cast<uint4*>(&g_Wt[(size_t)(c * 8 + i) * DU + v]) =
        *reinterpret_cast<const uint4*>(&sw[i][v]);
}

// ---------------------------------------------------------------------------
// persistent routing kernel: 3 iterations of (sgemm -> squash -> agree),
// separated by software grid barriers. 288 blocks x 256 threads, 2 CTAs/SM.
// ---------------------------------------------------------------------------
__global__ void __launch_bounds__(256, 2) k_routing(float* __restrict__ vout) {
    __shared__ __align__(16) char sb[11584];
    const int bid = blockIdx.x;
    const int t = threadIdx.x, lane = t & 31, w = t >> 5;
    unsigned epoch = 0;

    for (int it = 0; it < 3; it++) {
        // ================= phase S: split-K GEMM with fused exp =========
        {
            __half* As = reinterpret_cast<__half*>(sb);              // 64*SA halfs
            __half* Bs = reinterpret_cast<__half*>(sb + 64 * SA * 2);// 16*SB halfs
            float*  se = reinterpret_cast<float*>(sb + 64 * SA * 2 + 16 * SB * 2);
            const int ks = bid % KS, mt = bid / KS;
            const int m0 = mt * 64, k0 = ks * 128, cch0 = ks * 16;
            const int wm = w & 3, wn = w >> 2;

            if (t < 16 * NU) {
                const int cl = t / NU, d = t % NU;
                se[t] = __expf(__ldcg(&g_Bij[(cch0 + cl) * NU + d]));
            }
            __syncthreads();
            if (mt == 0 && t < NU) {
                float z = 0.0f;
#pragma unroll
                for (int cl = 0; cl < 16; cl++) z += se[cl * NU + t];
                atomicAdd(&g_Z[it * NU + t], z);
            }

            float acc[10][4];
#pragma unroll
            for (int i = 0; i < 10; i++)
#pragma unroll
                for (int j = 0; j < 4; j++) acc[i][j] = 0.0f;

            const uint32_t aaddr =
                smem_u32(&As[(wm * 16 + (lane & 15)) * SA + ((lane >> 4) << 3)]);
            const uint32_t baddr0 = smem_u32(&Bs[(lane & 15) * SB + wn * 80]);

            for (int kk = 0; kk < 8; kk++) {
                const int kg = k0 + kk * 16;
                if (t < 128) {
                    const int r = t >> 1, p = t & 1;
                    *reinterpret_cast<uint4*>(&As[r * SA + p * 8]) =
                        *reinterpret_cast<const uint4*>(
                            &g_Xh[(size_t)(m0 + r) * KK + kg + p * 8]);
                }
                for (int idx = t; idx < 320; idx += 256) {
                    const int kr = idx / 20, n8 = (idx % 20) * 8;
                    const int cl = kk * 2 + (kr >> 3), d = n8 >> 4;
                    const __half2 s2 = __float2half2_rn(se[cl * NU + d]);
                    uint4 raw = *reinterpret_cast<const uint4*>(
                        &g_Wt[(size_t)(kg + kr) * DU + n8]);
                    __half2* h = reinterpret_cast<__half2*>(&raw);
#pragma unroll
                    for (int j = 0; j < 4; j++) h[j] = __hmul2(h[j], s2);
                    *reinterpret_cast<uint4*>(&Bs[kr * SB + n8]) = raw;
                }
                __syncthreads();
                uint32_t a0, a1, a2, a3;
                ldsm_x4(a0, a1, a2, a3, aaddr);
#pragma unroll
                for (int nt = 0; nt < 10; nt++) {
                    uint32_t b0, b1;
                    ldsm_x2t(b0, b1, baddr0 + nt * 16);
                    mma16816(acc[nt][0], acc[nt][1], acc[nt][2], acc[nt][3],
                             a0, a1, a2, a3, b0, b1);
                }
                __syncthreads();
            }
            const int rg = lane >> 2, cb = (lane & 3) * 2;
            const int m = m0 + wm * 16 + rg;
#pragma unroll
            for (int nt = 0; nt < 10; nt++) {
                const int n = wn * 80 + nt * 8 + cb;
                float2 lo = make_float2(acc[nt][0], acc[nt][1]);
                float2 hi = make_float2(acc[nt][2], acc[nt][3]);
                *reinterpret_cast<float2*>(&g_Sp[((size_t)ks * BB + m) * DU + n]) = lo;
                *reinterpret_cast<float2*>(&g_Sp[((size_t)ks * BB + m + 8) * DU + n]) = hi;
            }
        }
        epoch++; grid_bar(epoch * GRID_R);

        // ================= phase Q: squash (blocks 0..255) ==============
        if (bid < BB) {
            float4* sred = reinterpret_cast<float4*>(sb);            // [6][40]
            float*  sv   = reinterpret_cast<float*>(sb + 6 * 40 * 16);
            float*  msq  = reinterpret_cast<float*>(sb + 6 * 40 * 16 + DU * 4);
            const int b = bid;
            const int du4 = t % 40, g = t / 40;   // g in [0,6) for t<240

            if (g < 6) {
                float4 s = make_float4(0.f, 0.f, 0.f, 0.f);
#pragma unroll
                for (int j = 0; j < 12; j++) {
                    const int ks = g * 12 + j;
                    const float4 p = __ldcg(reinterpret_cast<const float4*>(
                        &g_Sp[((size_t)ks * BB + b) * DU + du4 * 4]));
                    s.x += p.x; s.y += p.y; s.z += p.z; s.w += p.w;
                }
                sred[g * 40 + du4] = s;
            }
            __syncthreads();
            if (t < 40) {
                float4 a = sred[t];
#pragma unroll
                for (int g2 = 1; g2 < 6; g2++) {
                    const float4 p = sred[g2 * 40 + t];
                    a.x += p.x; a.y += p.y; a.z += p.z; a.w += p.w;
                }
                const float inv = 1.0f / __ldcg(&g_Z[it * NU + (t >> 2)]);
                a.x *= inv; a.y *= inv; a.z *= inv; a.w *= inv;
                *reinterpret_cast<float4*>(&sv[t * 4]) = a;
            }
            __syncthreads();
            if (t < US) {
                float m = 0.0f;
#pragma unroll
                for (int d = 0; d < NU; d++) {
                    const float v = sv[d * US + t];
                    m += v * v;
                }
                msq[t] = m;
            }
            __syncthreads();
            if (t < DU) {
                const float m = msq[t & 15];
                const float scale = sqrtf(m) / (1.0f + m);
                const float v = sv[t] * scale;
                vout[b * DU + t] = v;
                g_Vh[b * DU + t] = __float2half_rn(v);
            }
        }
        epoch++; grid_bar(epoch * GRID_R);

        // ================= phase A: agree (blocks 0..143) ===============
        if (it < 2) {
            if (bid < 144) {
                __half* As = reinterpret_cast<__half*>(sb);              // 128*SA
                __half* Bs = reinterpret_cast<__half*>(sb + 128 * SA * 2);
                const int mt = bid % 72, nb = bid / 72;
                const int m0 = mt * 128, n0 = nb * 80;

                float acc[10][4];
#pragma unroll
                for (int i = 0; i < 10; i++)
#pragma unroll
                    for (int j = 0; j < 4; j++) acc[i][j] = 0.0f;

                const uint32_t aaddr =
                    smem_u32(&As[(w * 16 + (lane & 15)) * SA + ((lane >> 4) << 3)]);
                const uint32_t baddr0 = smem_u32(&Bs[(lane & 15) * SB]);

                for (int kk = 0; kk < 16; kk++) {
                    const int kg = kk * 16;
                    {
                        const int r = t >> 1, p = t & 1;
                        *reinterpret_cast<uint4*>(&As[r * SA + p * 8]) =
                            *reinterpret_cast<const uint4*>(
                                &g_XhT[(size_t)(m0 + r) * BB + kg + p * 8]);
                    }
                    if (t < 160) {
                        const int kr = t / 10, n8 = (t % 10) * 8;
                        *reinterpret_cast<uint4*>(&Bs[kr * SB + n8]) =
                            __ldcg(reinterpret_cast<const uint4*>(
                                &g_Vh[(kg + kr) * DU + n0 + n8]));
                    }
                    __syncthreads();
                    uint32_t a0, a1, a2, a3;
                    ldsm_x4(a0, a1, a2, a3, aaddr);
#pragma unroll
                    for (int nt = 0; nt < 10; nt++) {
                        uint32_t b0, b1;
                        ldsm_x2t(b0, b1, baddr0 + nt * 16);
                        mma16816(acc[nt][0], acc[nt][1], acc[nt][2], acc[nt][3],
                                 a0, a1, a2, a3, b0, b1);
                    }
                    __syncthreads();
                }
                const int rg = lane >> 2, cb = (lane & 3) * 2;
                const int row0 = m0 + w * 16 + rg;
                float part[2][5];
#pragma unroll
                for (int cl = 0; cl < 2; cl++)
#pragma unroll
                    for (int dl = 0; dl < 5; dl++) part[cl][dl] = 0.0f;
#pragma unroll
                for (int nt = 0; nt < 10; nt++) {
                    const int dl = nt >> 1;
                    const int col = n0 + nt * 8 + cb;
                    const float2 f0 = __half22float2(
                        *reinterpret_cast<const __half2*>(&g_Wt[(size_t)row0 * DU + col]));
                    const float2 f1 = __half22float2(
                        *reinterpret_cast<const __half2*>(&g_Wt[(size_t)(row0 + 8) * DU + col]));
                    part[0][dl] += f0.x * acc[nt][0] + f0.y * acc[nt][1];
                    part[1][dl] += f1.x * acc[nt][2] + f1.y * acc[nt][3];
                }
#pragma unroll
                for (int cl = 0; cl < 2; cl++)
#pragma unroll
                    for (int dl = 0; dl < 5; dl++) {
                        float v = part[cl][dl];
#pragma unroll
                        for (int off = 16; off > 0; off >>= 1)
                            v += __shfl_xor_sync(0xffffffffu, v, off);
                        if (lane == 0) {
                            const int c = (m0 + w * 16) / 8 + cl;
                            const int d = nb * 5 + dl;
                            g_Bij[c * NU + d] += v * (1.0f / 256.0f);
                        }
                    }
            }
            epoch++; grid_bar(epoch * GRID_R);
        }
    }
}

// ---------------------------------------------------------------------------
extern "C" void kernel_launch(void* const* d_in, const int* in_sizes, int n_in,
                              void* d_out, int out_size) {
    const float* x;
    const float* W;
    if (in_sizes[0] == BB * IU * IC) {
        x = (const float*)d_in[0];
        W = (const float*)d_in[1];
    } else {
        W = (const float*)d_in[0];
        x = (const float*)d_in[1];
    }
    float* out = (float*)d_out;

    k_prep_x<<<dim3(IC / 32, BB / 64), 256>>>(x);
    k_prep_wt<<<IC, 160>>>(W);
    k_routing<<<GRID_R, 256>>>(out);
}